// round 11
// baseline (speedup 1.0000x reference)
#include <cuda_runtime.h>
#include <cstdint>

#define W_DIM 81920
#define N_DIM 4
#define C_DIM 64
#define O_DIM 64
#define K_DIM 10
#define TILE_W 256
#define TILES_PER_N (W_DIM / TILE_W)            // 320
#define NTILES      (N_DIM * TILES_PER_N)       // 1280
#define TBL_ELEMS   (W_DIM * K_DIM)             // 819200
#define PHASES 10
#define PITCHF 68                               // floats per smem row
#define PITCHB (PITCHF * 4)                     // 272 B
#define A_BYTES (TILE_W * PITCHB)               // 69632
#define B_BYTES (O_DIM * PITCHB)                // 17408
#define STAGE_BYTES (A_BYTES + B_BYTES)         // 87040
#define SM_BIAS 0
#define SM_STAGE 256
#define SMEM_BYTES (SM_STAGE + 2 * STAGE_BYTES) // 174336

// Static device scratch (no runtime allocation)
__device__ float g_xT[(size_t)N_DIM * W_DIM * C_DIM];  // [N,W,C], tf32-rounded
__device__ float g_wB[K_DIM * O_DIM * C_DIM];          // [k][o][c], tf32-rounded
__device__ int   g_idxT[TBL_ELEMS];                    // gather table [k][w]
__device__ int   g_is_i32;

__device__ __forceinline__ float to_tf32(float x) {
    asm("cvt.rna.tf32.f32 %0, %1;" : "=f"(x) : "f"(x));
    return x;
}

// ---------------------------------------------------------------------------
__global__ void detect_kernel(const int* __restrict__ t32) {
    __shared__ int f;
    if (threadIdx.x == 0) f = 0;
    __syncthreads();
    if (t32[2 * threadIdx.x + 1] != 0) atomicOr(&f, 1);
    __syncthreads();
    if (threadIdx.x == 0) g_is_i32 = f;
}

__global__ void convert_kernel(const int* __restrict__ t32) {
    int i = blockIdx.x * 256 + threadIdx.x;
    if (i < TBL_ELEMS) {
        int v = g_is_i32 ? t32[i] : t32[2 * i];
        int w = i / K_DIM;
        int k = i - w * K_DIM;
        g_idxT[k * W_DIM + w] = v;
    }
}

// input [N,C,W] -> g_xT [N,W,C] (tf32-rounded)
__global__ void transpose_kernel(const float* __restrict__ in) {
    __shared__ float t[32][33];
    int n  = blockIdx.z;
    int c0 = blockIdx.y << 5;
    int w0 = blockIdx.x << 5;
    int tx = threadIdx.x, ty = threadIdx.y;

    const size_t inb = ((size_t)n * C_DIM + c0) * W_DIM + w0;
#pragma unroll
    for (int i = 0; i < 32; i += 8)
        t[ty + i][tx] = in[inb + (size_t)(ty + i) * W_DIM + tx];
    __syncthreads();
    const size_t ob = ((size_t)n * W_DIM + w0) * C_DIM + c0;
#pragma unroll
    for (int i = 0; i < 32; i += 8)
        g_xT[ob + (size_t)(ty + i) * C_DIM + tx] = to_tf32(t[tx][ty + i]);
}

// weight [O,C,K,1] -> g_wB [k][o][c] (tf32-rounded)
__global__ void wprep_kernel(const float* __restrict__ w) {
    int i = blockIdx.x * 256 + threadIdx.x;
    if (i < O_DIM * C_DIM * K_DIM) {
        int o = i / (C_DIM * K_DIM);
        int r = i - o * (C_DIM * K_DIM);
        int c = r / K_DIM;
        int k = r - c * K_DIM;
        g_wB[(k * O_DIM + o) * C_DIM + c] = to_tf32(w[i]);
    }
}

// ---------------------------------------------------------------------------
// Conv: CTA tile 256w x 64o, cp.async double-buffered K-phases (64 each),
// tf32 mma.sync. 256 threads = 8 warps in 4(m) x 2(n), warp tile 64x32.
// ---------------------------------------------------------------------------
__global__ void __launch_bounds__(256, 1)
conv_kernel(const float* __restrict__ bias, float* __restrict__ out) {
    extern __shared__ char smem[];
    const unsigned sb = (unsigned)__cvta_generic_to_shared(smem);

    const int tid  = threadIdx.x;
    const int wid  = tid >> 5;
    const int lane = tid & 31;
    const int wr   = wid >> 1;          // warp row 0..3, m-offset 64*wr
    const int wn   = wid & 1;           // warp col 0..1, n-offset 32*wn

    if (tid < O_DIM)
        *reinterpret_cast<float*>(smem + SM_BIAS + tid * 4) = bias[tid];

    // ldmatrix per-lane source offsets (within a stage)
    const int lr = lane & 7;            // row within 8x8 matrix
    const int lm = lane >> 3;           // matrix id 0..3
    unsigned aoff[4], boff[2];
#pragma unroll
    for (int mt = 0; mt < 4; ++mt)      // A x4: {m_lo klo, m_hi klo, m_lo khi, m_hi khi}
        aoff[mt] = (unsigned)((wr * 64 + mt * 16 + (lm & 1) * 8 + lr) * PITCHB
                              + (lm >> 1) * 16);
#pragma unroll
    for (int bp = 0; bp < 2; ++bp)      // B x4: {o_lo klo, o_lo khi, o_hi klo, o_hi khi}
        boff[bp] = (unsigned)(A_BYTES
                              + (wn * 32 + bp * 16 + (lm >> 1) * 8 + lr) * PITCHB
                              + (lm & 1) * 16);

    // epilogue lane mapping (mma C layout)
    const int g2 = lane >> 2;           // C row within 8
    const int tg = lane & 3;            // C col pair

    const int arow = tid >> 4;          // loader helpers
    const int ac4  = tid & 15;
    __syncthreads();

    for (int t = blockIdx.x; t < NTILES; t += gridDim.x) {
        const int n  = t / TILES_PER_N;
        const int w0 = (t - n * TILES_PER_N) * TILE_W;
        const float* xTn = g_xT + (size_t)n * W_DIM * C_DIM;

        // ---- cp.async loader: phase p into stage s ----
        auto issue = [&](int p, int s) {
            const unsigned stg = sb + SM_STAGE + (unsigned)s * STAGE_BYTES;
            const int* idxp = g_idxT + p * W_DIM + w0;
#pragma unroll
            for (int j = 0; j < 16; ++j) {          // A: 4096 16B chunks
                int row = arow + 16 * j;
                int idx = idxp[row];
                unsigned sa = stg + (unsigned)(row * PITCHB + ac4 * 16);
                const float* ga = xTn + (size_t)idx * C_DIM + ac4 * 4;
                asm volatile("cp.async.cg.shared.global [%0], [%1], 16;"
                             :: "r"(sa), "l"(ga) : "memory");
            }
            const float* wp = g_wB + p * (O_DIM * C_DIM);
#pragma unroll
            for (int j = 0; j < 4; ++j) {           // B: 1024 16B chunks
                int lin = tid + 256 * j;
                int o   = lin >> 4;
                int c4  = lin & 15;
                unsigned sa = stg + (unsigned)(A_BYTES + o * PITCHB + c4 * 16);
                asm volatile("cp.async.cg.shared.global [%0], [%1], 16;"
                             :: "r"(sa), "l"(wp + o * C_DIM + c4 * 4) : "memory");
            }
            asm volatile("cp.async.commit_group;" ::: "memory");
        };

        issue(0, 0);

        float acc[4][4][4];
#pragma unroll
        for (int mt = 0; mt < 4; ++mt)
#pragma unroll
            for (int nt = 0; nt < 4; ++nt)
#pragma unroll
                for (int r = 0; r < 4; ++r) acc[mt][nt][r] = 0.0f;

        for (int p = 0; p < PHASES; ++p) {
            if (p < PHASES - 1) {
                issue(p + 1, (p + 1) & 1);
                asm volatile("cp.async.wait_group 1;" ::: "memory");
            } else {
                asm volatile("cp.async.wait_group 0;" ::: "memory");
            }
            __syncthreads();   // stage (p&1) fully visible

            const unsigned stg = sb + SM_STAGE + (unsigned)(p & 1) * STAGE_BYTES;
#pragma unroll
            for (int kk = 0; kk < 8; ++kk) {
                const unsigned kb = kk * 32;
                uint32_t a[4][4], b[4][2];
#pragma unroll
                for (int mt = 0; mt < 4; ++mt)
                    asm volatile(
                        "ldmatrix.sync.aligned.m8n8.x4.shared.b16 {%0,%1,%2,%3}, [%4];"
                        : "=r"(a[mt][0]), "=r"(a[mt][1]), "=r"(a[mt][2]), "=r"(a[mt][3])
                        : "r"(stg + aoff[mt] + kb));
#pragma unroll
                for (int bp = 0; bp < 2; ++bp)
                    asm volatile(
                        "ldmatrix.sync.aligned.m8n8.x4.shared.b16 {%0,%1,%2,%3}, [%4];"
                        : "=r"(b[2 * bp][0]), "=r"(b[2 * bp][1]),
                          "=r"(b[2 * bp + 1][0]), "=r"(b[2 * bp + 1][1])
                        : "r"(stg + boff[bp] + kb));
#pragma unroll
                for (int mt = 0; mt < 4; ++mt)
#pragma unroll
                    for (int nt = 0; nt < 4; ++nt)
                        asm volatile(
                            "mma.sync.aligned.m16n8k8.row.col.f32.tf32.tf32.f32 "
                            "{%0,%1,%2,%3}, {%4,%5,%6,%7}, {%8,%9}, {%0,%1,%2,%3};"
                            : "+f"(acc[mt][nt][0]), "+f"(acc[mt][nt][1]),
                              "+f"(acc[mt][nt][2]), "+f"(acc[mt][nt][3])
                            : "r"(a[mt][0]), "r"(a[mt][1]), "r"(a[mt][2]), "r"(a[mt][3]),
                              "r"(b[nt][0]), "r"(b[nt][1]));
            }
            __syncthreads();   // all reads of stage (p&1) done before overwrite
        }

        // ---- epilogue: bias + relu + store ----
        const float* sbias = reinterpret_cast<const float*>(smem + SM_BIAS);
#pragma unroll
        for (int nt = 0; nt < 4; ++nt) {
            const int o0 = wn * 32 + nt * 8 + 2 * tg;
            const float bz0 = sbias[o0], bz1 = sbias[o0 + 1];
            const size_t ob0 = ((size_t)n * O_DIM + o0) * W_DIM + w0;
            const size_t ob1 = ob0 + W_DIM;
#pragma unroll
            for (int mt = 0; mt < 4; ++mt) {
                const int wrow = wr * 64 + mt * 16 + g2;
                out[ob0 + wrow]     = fmaxf(acc[mt][nt][0] + bz0, 0.0f);
                out[ob1 + wrow]     = fmaxf(acc[mt][nt][1] + bz1, 0.0f);
                out[ob0 + wrow + 8] = fmaxf(acc[mt][nt][2] + bz0, 0.0f);
                out[ob1 + wrow + 8] = fmaxf(acc[mt][nt][3] + bz1, 0.0f);
            }
        }
        // stage reuse safe: last reads guarded by trailing __syncthreads() above
    }
}

// ---------------------------------------------------------------------------
extern "C" void kernel_launch(void* const* d_in, const int* in_sizes, int n_in,
                              void* d_out, int out_size) {
    const float* input  = (const float*)d_in[0];
    const int*   tbl32  = (const int*)d_in[1];
    const float* weight = (const float*)d_in[2];
    const float* bias   = (const float*)d_in[3];
    float*       out    = (float*)d_out;

    cudaFuncSetAttribute(conv_kernel,
                         cudaFuncAttributeMaxDynamicSharedMemorySize, SMEM_BYTES);

    int dev = 0;
    cudaGetDevice(&dev);
    int nsm = 148;
    cudaDeviceGetAttribute(&nsm, cudaDevAttrMultiProcessorCount, dev);

    detect_kernel<<<1, 64>>>(tbl32);
    convert_kernel<<<(TBL_ELEMS + 255) / 256, 256>>>(tbl32);
    transpose_kernel<<<dim3(W_DIM / 32, C_DIM / 32, N_DIM), dim3(32, 8)>>>(input);
    wprep_kernel<<<(O_DIM * C_DIM * K_DIM + 255) / 256, 256>>>(weight);
    conv_kernel<<<nsm, 256, SMEM_BYTES>>>(bias, out);
}

// round 12
// speedup vs baseline: 1.8881x; 1.8881x over previous
#include <cuda_runtime.h>
#include <cuda_fp16.h>
#include <cstdint>

#define W_DIM 81920
#define N_DIM 4
#define C_DIM 64
#define O_DIM 64
#define K_DIM 10
#define TILE_W 128
#define TILES_PER_N (W_DIM / TILE_W)            // 640
#define NTILES      (N_DIM * TILES_PER_N)       // 2560
#define TBL_ELEMS   (W_DIM * K_DIM)             // 819200
#define PHASES 10
#define NSTAGE 3
#define PITCHB 144                              // 128B row + 16B pad
#define A_BYTES (TILE_W * PITCHB)               // 18432
#define B_BYTES (O_DIM * PITCHB)                // 9216
#define STAGE_BYTES (A_BYTES + B_BYTES)         // 27648
#define SM_BIAS 0
#define SM_STAGE 256
#define SMEM_BYTES (SM_STAGE + NSTAGE * STAGE_BYTES)  // 83200

// Static device scratch (no runtime allocation)
__device__ __half g_xH[(size_t)N_DIM * W_DIM * C_DIM];  // [N,W,C] fp16
__device__ __half g_wH[K_DIM * O_DIM * C_DIM];          // [k][o][c] fp16
__device__ int    g_idxT[TBL_ELEMS];                    // gather table [k][w]
__device__ int    g_is_i32;

// ---------------------------------------------------------------------------
__global__ void detect_kernel(const int* __restrict__ t32) {
    __shared__ int f;
    if (threadIdx.x == 0) f = 0;
    __syncthreads();
    if (t32[2 * threadIdx.x + 1] != 0) atomicOr(&f, 1);
    __syncthreads();
    if (threadIdx.x == 0) g_is_i32 = f;
}

__global__ void convert_kernel(const int* __restrict__ t32) {
    int i = blockIdx.x * 256 + threadIdx.x;
    if (i < TBL_ELEMS) {
        int v = g_is_i32 ? t32[i] : t32[2 * i];
        int w = i / K_DIM;
        int k = i - w * K_DIM;
        g_idxT[k * W_DIM + w] = v;
    }
}

// input [N,C,W] -> g_xH [N,W,C] (fp16)
__global__ void transpose_kernel(const float* __restrict__ in) {
    __shared__ float t[32][33];
    int n  = blockIdx.z;
    int c0 = blockIdx.y << 5;
    int w0 = blockIdx.x << 5;
    int tx = threadIdx.x, ty = threadIdx.y;

    const size_t inb = ((size_t)n * C_DIM + c0) * W_DIM + w0;
#pragma unroll
    for (int i = 0; i < 32; i += 8)
        t[ty + i][tx] = in[inb + (size_t)(ty + i) * W_DIM + tx];
    __syncthreads();
    const size_t ob = ((size_t)n * W_DIM + w0) * C_DIM + c0;
#pragma unroll
    for (int i = 0; i < 32; i += 8)
        g_xH[ob + (size_t)(ty + i) * C_DIM + tx] = __float2half(t[tx][ty + i]);
}

// weight [O,C,K,1] -> g_wH [k][o][c] (fp16)
__global__ void wprep_kernel(const float* __restrict__ w) {
    int i = blockIdx.x * 256 + threadIdx.x;
    if (i < O_DIM * C_DIM * K_DIM) {
        int o = i / (C_DIM * K_DIM);
        int r = i - o * (C_DIM * K_DIM);
        int c = r / K_DIM;
        int k = r - c * K_DIM;
        g_wH[(k * O_DIM + o) * C_DIM + c] = __float2half(w[i]);
    }
}

// ---------------------------------------------------------------------------
// Conv: tile 128w x 64o, 3-stage cp.async pipeline over 10 K-phases (64 each),
// fp16 mma.sync m16n8k16, f32 accum. 8 warps in 4(m) x 2(n), warp tile 32x32.
// ---------------------------------------------------------------------------
__global__ void __launch_bounds__(256, 2)
conv_kernel(const float* __restrict__ bias, float* __restrict__ out) {
    extern __shared__ char smem[];
    const unsigned sb = (unsigned)__cvta_generic_to_shared(smem);

    const int tid  = threadIdx.x;
    const int wid  = tid >> 5;
    const int lane = tid & 31;
    const int wr   = wid >> 1;          // warp row 0..3 (m offset 32*wr)
    const int wn   = wid & 1;           // warp col 0..1 (n offset 32*wn)

    if (tid < O_DIM)
        *reinterpret_cast<float*>(smem + SM_BIAS + tid * 4) = bias[tid];

    // ldmatrix per-lane source offsets (within a stage)
    const int lr = lane & 7;            // row within 8x8 matrix
    const int lm = lane >> 3;           // matrix id 0..3
    // A x4: matrices {m-lo k-lo, m-hi k-lo, m-lo k-hi, m-hi k-hi}
    unsigned aoff[2];
#pragma unroll
    for (int mt = 0; mt < 2; ++mt)
        aoff[mt] = (unsigned)((wr * 32 + mt * 16 + (lm & 1) * 8 + lr) * PITCHB
                              + (lm >> 1) * 16);
    // B x4: matrices {n-lo k-lo, n-lo k-hi, n-hi k-lo, n-hi k-hi}
    unsigned boff[2];
#pragma unroll
    for (int bp = 0; bp < 2; ++bp)
        boff[bp] = (unsigned)(A_BYTES
                              + (wn * 32 + bp * 16 + (lm >> 1) * 8 + lr) * PITCHB
                              + (lm & 1) * 16);

    // epilogue lane mapping (mma C layout)
    const int g2 = lane >> 2;
    const int tg = lane & 3;

    const int arow = tid >> 3;          // loader: A row base (0..31)
    const int ac8  = tid & 7;           // loader: 16B chunk in row
    __syncthreads();

    for (int t = blockIdx.x; t < NTILES; t += gridDim.x) {
        const int n  = t / TILES_PER_N;
        const int w0 = (t - n * TILES_PER_N) * TILE_W;
        const __half* xHn = g_xH + (size_t)n * W_DIM * C_DIM;

        // ---- cp.async loader: phase p into stage s ----
        auto issue = [&](int p, int s) {
            const unsigned stg = sb + SM_STAGE + (unsigned)s * STAGE_BYTES;
            const int* idxp = g_idxT + p * W_DIM + w0;
#pragma unroll
            for (int j = 0; j < 4; ++j) {           // A: 1024 16B chunks
                int row = arow + 32 * j;
                int idx = idxp[row];
                unsigned sa = stg + (unsigned)(row * PITCHB + ac8 * 16);
                const __half* ga = xHn + (size_t)idx * C_DIM + ac8 * 8;
                asm volatile("cp.async.cg.shared.global [%0], [%1], 16;"
                             :: "r"(sa), "l"(ga) : "memory");
            }
            const __half* wp = g_wH + p * (O_DIM * C_DIM);
#pragma unroll
            for (int j = 0; j < 2; ++j) {           // B: 512 16B chunks
                int lin = tid + 256 * j;
                int o   = lin >> 3;
                int c8  = lin & 7;
                unsigned sa = stg + (unsigned)(A_BYTES + o * PITCHB + c8 * 16);
                asm volatile("cp.async.cg.shared.global [%0], [%1], 16;"
                             :: "r"(sa), "l"(wp + o * C_DIM + c8 * 8) : "memory");
            }
            asm volatile("cp.async.commit_group;" ::: "memory");
        };

        issue(0, 0);
        issue(1, 1);

        float acc[2][4][4];
#pragma unroll
        for (int mt = 0; mt < 2; ++mt)
#pragma unroll
            for (int nt = 0; nt < 4; ++nt)
#pragma unroll
                for (int r = 0; r < 4; ++r) acc[mt][nt][r] = 0.0f;

        for (int p = 0; p < PHASES; ++p) {
            if (p < PHASES - 1)
                asm volatile("cp.async.wait_group 1;" ::: "memory");
            else
                asm volatile("cp.async.wait_group 0;" ::: "memory");
            __syncthreads();   // group p complete + prior-phase reads done

            const unsigned stg = sb + SM_STAGE
                               + (unsigned)(p % NSTAGE) * STAGE_BYTES;
#pragma unroll
            for (int kk = 0; kk < 4; ++kk) {        // k16 steps
                const unsigned kb = kk * 32;
                uint32_t a[2][4], b[4][2];
#pragma unroll
                for (int mt = 0; mt < 2; ++mt)
                    asm volatile(
                        "ldmatrix.sync.aligned.m8n8.x4.shared.b16 {%0,%1,%2,%3}, [%4];"
                        : "=r"(a[mt][0]), "=r"(a[mt][1]), "=r"(a[mt][2]), "=r"(a[mt][3])
                        : "r"(stg + aoff[mt] + kb));
#pragma unroll
                for (int bp = 0; bp < 2; ++bp)
                    asm volatile(
                        "ldmatrix.sync.aligned.m8n8.x4.shared.b16 {%0,%1,%2,%3}, [%4];"
                        : "=r"(b[2 * bp][0]), "=r"(b[2 * bp][1]),
                          "=r"(b[2 * bp + 1][0]), "=r"(b[2 * bp + 1][1])
                        : "r"(stg + boff[bp] + kb));
#pragma unroll
                for (int mt = 0; mt < 2; ++mt)
#pragma unroll
                    for (int nt = 0; nt < 4; ++nt)
                        asm volatile(
                            "mma.sync.aligned.m16n8k16.row.col.f32.f16.f16.f32 "
                            "{%0,%1,%2,%3}, {%4,%5,%6,%7}, {%8,%9}, {%0,%1,%2,%3};"
                            : "+f"(acc[mt][nt][0]), "+f"(acc[mt][nt][1]),
                              "+f"(acc[mt][nt][2]), "+f"(acc[mt][nt][3])
                            : "r"(a[mt][0]), "r"(a[mt][1]), "r"(a[mt][2]), "r"(a[mt][3]),
                              "r"(b[nt][0]), "r"(b[nt][1]));
            }

            if (p + 2 < PHASES)
                issue(p + 2, (p + 2) % NSTAGE);
        }

        // ---- epilogue: bias + relu + store ----
        const float* sbias = reinterpret_cast<const float*>(smem + SM_BIAS);
#pragma unroll
        for (int nt = 0; nt < 4; ++nt) {
            const int o0 = wn * 32 + nt * 8 + 2 * tg;
            const float bz0 = sbias[o0], bz1 = sbias[o0 + 1];
            const size_t ob0 = ((size_t)n * O_DIM + o0) * W_DIM + w0;
            const size_t ob1 = ob0 + W_DIM;
#pragma unroll
            for (int mt = 0; mt < 2; ++mt) {
                const int wrow = wr * 32 + mt * 16 + g2;
                out[ob0 + wrow]     = fmaxf(acc[mt][nt][0] + bz0, 0.0f);
                out[ob1 + wrow]     = fmaxf(acc[mt][nt][1] + bz1, 0.0f);
                out[ob0 + wrow + 8] = fmaxf(acc[mt][nt][2] + bz0, 0.0f);
                out[ob1 + wrow + 8] = fmaxf(acc[mt][nt][3] + bz1, 0.0f);
            }
        }
        __syncthreads();   // phase-9 stage (0) fully read before next tile's issue(0,0)
    }
}

// ---------------------------------------------------------------------------
extern "C" void kernel_launch(void* const* d_in, const int* in_sizes, int n_in,
                              void* d_out, int out_size) {
    const float* input  = (const float*)d_in[0];
    const int*   tbl32  = (const int*)d_in[1];
    const float* weight = (const float*)d_in[2];
    const float* bias   = (const float*)d_in[3];
    float*       out    = (float*)d_out;

    cudaFuncSetAttribute(conv_kernel,
                         cudaFuncAttributeMaxDynamicSharedMemorySize, SMEM_BYTES);

    int dev = 0;
    cudaGetDevice(&dev);
    int nsm = 148;
    cudaDeviceGetAttribute(&nsm, cudaDevAttrMultiProcessorCount, dev);

    detect_kernel<<<1, 64>>>(tbl32);
    convert_kernel<<<(TBL_ELEMS + 255) / 256, 256>>>(tbl32);
    transpose_kernel<<<dim3(W_DIM / 32, C_DIM / 32, N_DIM), dim3(32, 8)>>>(input);
    wprep_kernel<<<(O_DIM * C_DIM * K_DIM + 255) / 256, 256>>>(weight);
    conv_kernel<<<2 * nsm, 256, SMEM_BYTES>>>(bias, out);
}